// round 2
// baseline (speedup 1.0000x reference)
#include <cuda_runtime.h>
#include <math.h>

// Problem constants
#define NN 1024     // nodes
#define TT 64       // time dim
#define BB 32       // batch
#define DD 64       // embed dim
#define FT 64       // feature out
#define BT 2048     // BB*TT
#define NCH 5       // effective channels: [X, S0X, S1X, T2(S0)X, T2(S1)X]
#define WCOLS (NCH*TT*FT)   // 20480

// ---------------- scratch (device globals; no runtime allocation) ----------
__device__ float g_Xbuf[NN*BT];                 // 8 MB   X (node-major), reused as X2
__device__ float g_Ybuf[4*NN*BT];               // 33.5MB [Y1_0; Y1_1; Y2_0; Y2_1], also L-temp
__device__ float g_Scat[2*NN*NN];               // 8 MB   [S0; S1]
__device__ float g_Wmod[DD*WCOLS];              // 5.2MB  gathered weight view
__device__ float g_Wcat[(size_t)NN*WCOLS];      // 84 MB  per-node generated weights
__device__ float g_Obuf[NN*BB*FT];              // 8.4MB  contraction output [n][b][o]
__device__ float g_bias[NN*FT];
__device__ float g_ET[DD*NN];

// ---------------- generic SGEMM: C[z] = alpha*A[z]@B[z] (- sub) -----------
// Row-major. tile 128x128x8, 256 thr, 8x8 micro-tile. All dims multiple of 128/8.
__global__ __launch_bounds__(256) void sgemm_k(
    const float* __restrict__ A, const float* __restrict__ B, float* __restrict__ C,
    const float* __restrict__ sub, int N, int K, float alpha,
    long Abat, long Bbat, long Cbat)
{
    __shared__ float As[8][128];
    __shared__ float Bs[8][128];
    const int tid = threadIdx.x;
    const float* Ap = A + Abat*blockIdx.z + (long)(blockIdx.y*128)*K;
    const float* Bp = B + Bbat*blockIdx.z + blockIdx.x*128;
    float* Cp = C + Cbat*blockIdx.z;

    float acc[8][8];
#pragma unroll
    for (int i=0;i<8;i++)
#pragma unroll
        for (int j=0;j<8;j++) acc[i][j]=0.f;

    const int arow = tid>>1, acol=(tid&1)*4;
    const int brow = tid>>5, bcol=(tid&31)*4;
    const int ty = tid>>4, tx = tid&15;

    for (int k0=0;k0<K;k0+=8){
        float4 av = *(const float4*)(Ap + (long)arow*K + k0 + acol);
        As[acol+0][arow]=av.x; As[acol+1][arow]=av.y;
        As[acol+2][arow]=av.z; As[acol+3][arow]=av.w;
        *(float4*)&Bs[brow][bcol] = *(const float4*)(Bp + (long)(k0+brow)*N + bcol);
        __syncthreads();
#pragma unroll
        for (int kk=0;kk<8;kk++){
            float a[8],b[8];
#pragma unroll
            for(int i=0;i<8;i++) a[i]=As[kk][ty*8+i];
#pragma unroll
            for(int j=0;j<8;j++) b[j]=Bs[kk][tx*8+j];
#pragma unroll
            for(int i=0;i<8;i++)
#pragma unroll
                for(int j=0;j<8;j++) acc[i][j] = fmaf(a[i],b[j],acc[i][j]);
        }
        __syncthreads();
    }
#pragma unroll
    for(int i=0;i<8;i++){
        int row = blockIdx.y*128 + ty*8 + i;
#pragma unroll
        for(int j=0;j<8;j+=4){
            int col = blockIdx.x*128 + tx*8 + j;
            float4 v;
            v.x = alpha*acc[i][j];   v.y = alpha*acc[i][j+1];
            v.z = alpha*acc[i][j+2]; v.w = alpha*acc[i][j+3];
            if (sub){
                const float* s = sub + (long)row*N + col;
                v.x -= s[0]; v.y -= s[1]; v.z -= s[2]; v.w -= s[3];
            }
            *(float4*)(Cp + (long)row*N + col) = v;
        }
    }
}

// ---------------- row softmax of relu(row) over 1024 cols ------------------
__global__ void relu_softmax_k(const float* __restrict__ in, float* __restrict__ out){
    const int row = blockIdx.x;
    const int tid = threadIdx.x;  // 256
    __shared__ float red[256];
    const float* r = in + (long)row*NN;
    float mx = 0.f;
    for (int j=tid;j<NN;j+=256) mx = fmaxf(mx, r[j]);
    red[tid]=mx; __syncthreads();
    for (int s=128;s>0;s>>=1){ if(tid<s) red[tid]=fmaxf(red[tid],red[tid+s]); __syncthreads(); }
    mx = fmaxf(red[0], 0.f);
    __syncthreads();
    float sum=0.f;
    for (int j=tid;j<NN;j+=256) sum += expf(fmaxf(r[j],0.f)-mx);
    red[tid]=sum; __syncthreads();
    for (int s=128;s>0;s>>=1){ if(tid<s) red[tid]+=red[tid+s]; __syncthreads(); }
    float inv = 1.f/red[0];
    for (int j=tid;j<NN;j+=256) out[(long)row*NN+j] = expf(fmaxf(r[j],0.f)-mx)*inv;
}

// ---------------- x[B,N,T] -> X[N, B*T] (float4 copy) ----------------------
__global__ void txpose_x_k(const float* __restrict__ x, float* __restrict__ X){
    int idx = blockIdx.x*256 + threadIdx.x;   // n*512 + b*16 + t4
    int n = idx >> 9;
    int bt4 = idx & 511;
    int b = bt4 >> 4;
    int t4 = bt4 & 15;
    ((float4*)X)[idx] = ((const float4*)x)[((long)b*NN + n)*16 + t4];
}

// ---------------- E[N,D] -> ET[D,N] ---------------------------------------
__global__ void tE_k(const float* __restrict__ E, float* __restrict__ ET){
    int idx = blockIdx.x*256+threadIdx.x;  // 65536
    int n = idx>>6, d = idx&63;
    ET[d*NN+n]=E[idx];
}

// ---------------- gather W[G,D,K,T,Ft] -> Wmod[D, 5*T*Ft] ------------------
// ch0 = W[0,:,0]+W[1,:,0]; ch1=(g0,k1); ch2=(g1,k1); ch3=(g0,k2); ch4=(g1,k2)
__global__ void wmod_k(const float* __restrict__ W, float* __restrict__ Wm){
    int idx = blockIdx.x*256 + threadIdx.x;
    if (idx >= DD*WCOLS) return;
    int d = idx / WCOLS;
    int r = idx - d*WCOLS;
    int ch = r >> 12;       // /4096
    int to = r & 4095;
    float val;
    if (ch==0){
        val = W[(long)(d*3)*4096 + to] + W[(long)((64+d)*3)*4096 + to];
    } else {
        int g = (ch-1)&1;
        int k = 1 + ((ch-1)>>1);
        val = W[(long)((g*64+d)*3+k)*4096 + to];
    }
    Wm[idx] = val;
}

// ---------------- bias[n,o] = E[n,:] @ (bp[0]+bp[1]) -----------------------
__global__ void bias_k(const float* __restrict__ E, const float* __restrict__ bp,
                       float* __restrict__ bias){
    int n = blockIdx.x, o = threadIdx.x; // 64
    float s = 0.f;
    for (int d=0; d<64; d++) s += E[n*64+d]*(bp[d*64+o] + bp[4096 + d*64+o]);
    bias[n*64+o]=s;
}

// ---------------- per-node contraction: O[n,b,o] = sum_{ch,t} ... ----------
__global__ __launch_bounds__(256) void contract_k(
    const float* __restrict__ X, const float* __restrict__ Y,
    const float* __restrict__ Wc, const float* __restrict__ bias,
    float* __restrict__ O)
{
    const int n = blockIdx.x;
    const int tid = threadIdx.x;
    __shared__ float Xs[2048];   // [b][t]
    __shared__ float Ws[4096];   // [t][o]
    float acc[8]={0.f,0.f,0.f,0.f,0.f,0.f,0.f,0.f};
    const int b = tid>>3;
    const int ob = (tid&7)*8;
    for (int ch=0; ch<NCH; ch++){
        const float4* s4 = (const float4*)((ch==0)? X + (long)n*BT
                                                  : Y + ((long)(ch-1)*NN + n)*BT);
        ((float4*)Xs)[tid]     = s4[tid];
        ((float4*)Xs)[tid+256] = s4[tid+256];
        const float4* w4 = (const float4*)(Wc + (long)n*WCOLS + ch*4096);
#pragma unroll
        for (int q=0;q<4;q++) ((float4*)Ws)[tid + q*256] = w4[tid + q*256];
        __syncthreads();
#pragma unroll
        for (int t=0;t<64;t++){
            float xv = Xs[b*64+t];
            float4 w0 = *(const float4*)&Ws[t*64+ob];
            float4 w1 = *(const float4*)&Ws[t*64+ob+4];
            acc[0]=fmaf(xv,w0.x,acc[0]); acc[1]=fmaf(xv,w0.y,acc[1]);
            acc[2]=fmaf(xv,w0.z,acc[2]); acc[3]=fmaf(xv,w0.w,acc[3]);
            acc[4]=fmaf(xv,w1.x,acc[4]); acc[5]=fmaf(xv,w1.y,acc[5]);
            acc[6]=fmaf(xv,w1.z,acc[6]); acc[7]=fmaf(xv,w1.w,acc[7]);
        }
        __syncthreads();
    }
    float* o = O + ((long)n*BB + b)*FT + ob;
    const float* bi = bias + n*FT + ob;
#pragma unroll
    for (int j=0;j<8;j++) o[j] = acc[j] + bi[j];
}

// ---------------- layer1 epilogue: proj Ft->T, LN, relu, write transposed --
__global__ void proj_ln_relu_k(const float* __restrict__ O, const float* __restrict__ pw,
                               const float* __restrict__ pb, const float* __restrict__ gam,
                               const float* __restrict__ bet, float* __restrict__ Xout)
{
    const int nb = blockIdx.x;       // n*32+b
    const int t = threadIdx.x;       // 64
    __shared__ float v[64], r1[64], r2[64];
    v[t] = O[(long)nb*64 + t];
    __syncthreads();
    float h = pb[t];
#pragma unroll
    for (int o=0;o<64;o++) h = fmaf(v[o], pw[o*64+t], h);
    r1[t]=h; r2[t]=h*h; __syncthreads();
    for (int s=32;s>0;s>>=1){ if(t<s){ r1[t]+=r1[t+s]; r2[t]+=r2[t+s]; } __syncthreads(); }
    float m = r1[0]*0.015625f;
    float var = r2[0]*0.015625f - m*m;
    float y = (h-m)*rsqrtf(var+1e-5f)*gam[t]+bet[t];
    y = fmaxf(y,0.f);
    const int n = nb>>5, b = nb&31;
    Xout[(long)n*BT + b*64 + t] = y;
}

// ---------------- layer2 epilogue: proj, +sig(res_gate)*x, LN, write out ---
__global__ void final_k(const float* __restrict__ O, const float* __restrict__ pw,
                        const float* __restrict__ pb, const float* __restrict__ x,
                        const float* __restrict__ rg, const float* __restrict__ gam,
                        const float* __restrict__ bet, float* __restrict__ out)
{
    const int nb = blockIdx.x;
    const int t = threadIdx.x;
    const int n = nb>>5, b = nb&31;
    __shared__ float v[64], r1[64], r2[64];
    v[t]=O[(long)nb*64+t];
    __syncthreads();
    float h = pb[t];
#pragma unroll
    for (int o=0;o<64;o++) h = fmaf(v[o], pw[o*64+t], h);
    float sg = 1.f/(1.f+expf(-rg[0]));
    h = fmaf(sg, x[((long)b*NN+n)*64 + t], h);
    r1[t]=h; r2[t]=h*h; __syncthreads();
    for (int s=32;s>0;s>>=1){ if(t<s){ r1[t]+=r1[t+s]; r2[t]+=r2[t+s]; } __syncthreads(); }
    float m=r1[0]*0.015625f, var=r2[0]*0.015625f-m*m;
    out[((long)b*NN+n)*64+t] = (h-m)*rsqrtf(var+1e-5f)*gam[t]+bet[t];
}

// ===========================================================================
extern "C" void kernel_launch(void* const* d_in, const int* in_sizes, int n_in,
                              void* d_out, int out_size)
{
    const float* x     = (const float*)d_in[0];
    const float* A_fix = (const float*)d_in[1];
    const float* E     = (const float*)d_in[2];
    const float* W1    = (const float*)d_in[3];
    const float* b1p   = (const float*)d_in[4];
    const float* W2    = (const float*)d_in[5];
    const float* b2p   = (const float*)d_in[6];
    const float* p1w   = (const float*)d_in[7];
    const float* p1b   = (const float*)d_in[8];
    const float* p2w   = (const float*)d_in[9];
    const float* p2b   = (const float*)d_in[10];
    const float* g1    = (const float*)d_in[11];
    const float* be1   = (const float*)d_in[12];
    const float* g2    = (const float*)d_in[13];
    const float* be2   = (const float*)d_in[14];
    const float* rg    = (const float*)d_in[15];
    float* out = (float*)d_out;

    float *Xb,*Yb,*Sc,*Wm,*Wc,*Ob,*Bi,*ETp;
    cudaGetSymbolAddress((void**)&Xb,  g_Xbuf);
    cudaGetSymbolAddress((void**)&Yb,  g_Ybuf);
    cudaGetSymbolAddress((void**)&Sc,  g_Scat);
    cudaGetSymbolAddress((void**)&Wm,  g_Wmod);
    cudaGetSymbolAddress((void**)&Wc,  g_Wcat);
    cudaGetSymbolAddress((void**)&Ob,  g_Obuf);
    cudaGetSymbolAddress((void**)&Bi,  g_bias);
    cudaGetSymbolAddress((void**)&ETp, g_ET);

    // --- shared precompute: supports ---
    tE_k<<<256,256>>>(E, ETp);
    // L = E @ E^T  (temp in Ybuf)
    sgemm_k<<<dim3(8,8,1),256>>>(E, ETp, Yb, nullptr, 1024, 64, 1.f, 0,0,0);
    relu_softmax_k<<<1024,256>>>(Yb,    Sc);              // S0 = softmax(relu(EE^T))
    relu_softmax_k<<<1024,256>>>(A_fix, Sc + (long)NN*NN);// S1 = softmax(clip(A,0))

    // --- X (node-major) ---
    txpose_x_k<<<2048,256>>>(x, Xb);

    // --- layer 1 ---
    wmod_k<<<(DD*WCOLS+255)/256,256>>>(W1, Wm);
    sgemm_k<<<dim3(160,8,1),256>>>(E, Wm, Wc, nullptr, WCOLS, 64, 1.f, 0,0,0);
    bias_k<<<1024,64>>>(E, b1p, Bi);
    // Y1 = [S0;S1] @ X   (M=2048, N=2048, K=1024)
    sgemm_k<<<dim3(16,16,1),256>>>(Sc, Xb, Yb, nullptr, BT, 1024, 1.f, 0,0,0);
    // Y2_g = 2*S_g@Y1_g - X   (z-batched over g)
    sgemm_k<<<dim3(16,8,2),256>>>(Sc, Yb, Yb + 2L*NN*BT, Xb, BT, 1024, 2.f,
                                  (long)NN*NN, (long)NN*BT, (long)NN*BT);
    contract_k<<<1024,256>>>(Xb, Yb, Wc, Bi, Ob);
    proj_ln_relu_k<<<NN*BB,64>>>(Ob, p1w, p1b, g1, be1, Xb);   // writes X2 transposed

    // --- layer 2 ---
    wmod_k<<<(DD*WCOLS+255)/256,256>>>(W2, Wm);
    sgemm_k<<<dim3(160,8,1),256>>>(E, Wm, Wc, nullptr, WCOLS, 64, 1.f, 0,0,0);
    bias_k<<<1024,64>>>(E, b2p, Bi);
    sgemm_k<<<dim3(16,16,1),256>>>(Sc, Xb, Yb, nullptr, BT, 1024, 1.f, 0,0,0);
    sgemm_k<<<dim3(16,8,2),256>>>(Sc, Yb, Yb + 2L*NN*BT, Xb, BT, 1024, 2.f,
                                  (long)NN*NN, (long)NN*BT, (long)NN*BT);
    contract_k<<<1024,256>>>(Xb, Yb, Wc, Bi, Ob);
    final_k<<<NN*BB,64>>>(Ob, p2w, p2b, x, rg, g2, be2, out);
}

// round 6
// speedup vs baseline: 1.5814x; 1.5814x over previous
#include <cuda_runtime.h>
#include <cuda_bf16.h>
#include <math.h>
#include <stdint.h>

// Problem constants
#define NN 1024
#define TT 64
#define BB 32
#define DD 64
#define FT 64
#define BT 2048
#define NCH 5
#define WCOLS (NCH*TT*FT)   // 20480

// ---------------- scratch (device globals) ---------------------------------
__device__ float g_Xbuf[NN*BT];
__device__ float g_Ybuf[4*NN*BT];
__device__ float g_Scat[2*NN*NN];
__device__ float g_Wmod[DD*WCOLS];
__device__ float g_Wcat[(size_t)NN*WCOLS];
__device__ float g_Obuf[NN*BB*FT];
__device__ float g_bias[NN*FT];
__device__ float g_ET[DD*NN];
// split-bf16 operand planes
__device__ __nv_bfloat16 g_SH[2048*1024];
__device__ __nv_bfloat16 g_SL[2048*1024];
__device__ __nv_bfloat16 g_BH[2*2048*1024];
__device__ __nv_bfloat16 g_BL[2*2048*1024];

// ---------------- helpers ---------------------------------------------------
__device__ __forceinline__ uint32_t s2u(const void* p){
    uint32_t a;
    asm("{ .reg .u64 t; cvta.to.shared.u64 t, %1; cvt.u32.u64 %0, t; }" : "=r"(a) : "l"(p));
    return a;
}
__device__ __forceinline__ void cp16(uint32_t s, const void* g){
    asm volatile("cp.async.cg.shared.global [%0], [%1], 16;" :: "r"(s), "l"(g));
}
__device__ __forceinline__ void ldsm4(uint32_t* r, uint32_t a){
    asm volatile("ldmatrix.sync.aligned.m8n8.x4.shared.b16 {%0,%1,%2,%3}, [%4];"
        : "=r"(r[0]), "=r"(r[1]), "=r"(r[2]), "=r"(r[3]) : "r"(a));
}
__device__ __forceinline__ void mma16816(float* d, const uint32_t* a, uint32_t b0, uint32_t b1){
    asm volatile("mma.sync.aligned.m16n8k16.row.col.f32.bf16.bf16.f32 "
        "{%0,%1,%2,%3}, {%4,%5,%6,%7}, {%8,%9}, {%0,%1,%2,%3};"
        : "+f"(d[0]), "+f"(d[1]), "+f"(d[2]), "+f"(d[3])
        : "r"(a[0]), "r"(a[1]), "r"(a[2]), "r"(a[3]), "r"(b0), "r"(b1));
}

// ============ split-bf16 GEMM on mma.sync (sm_100-safe tensor cores) ========
// C[rows,2048] = alpha * (A @ Bt^T) (- sub), 3-segment split bf16, K'=3072.
// A planes [rowsTot,1024] K-major; Bt planes [2048,1024] K-major (row = out col).
// grid (16, Mtiles, z), 256 thr. CTA tile 128x128, warp 32x64, k-tile 64.
__global__ void __launch_bounds__(256) gemm_mma_k(
    const __nv_bfloat16* __restrict__ Ah, const __nv_bfloat16* __restrict__ Al,
    const __nv_bfloat16* __restrict__ Bh, const __nv_bfloat16* __restrict__ Bl,
    float* __restrict__ C, const float* __restrict__ sub,
    float alpha, int AzRows, long Bbat, long Cbat)
{
    extern __shared__ __align__(16) char smraw[];
    const uint32_t sA = s2u(smraw);              // [2][128][64] bf16 = 2x16KB
    const uint32_t sB = sA + 32768;              // [2][128][64] bf16

    const int tid  = threadIdx.x;
    const int wid  = tid >> 5;
    const int lane = tid & 31;
    const int wm   = wid >> 1;          // 0..3
    const int wn   = wid & 1;           // 0..1

    const long aRow0 = (long)blockIdx.z*AzRows + (long)blockIdx.y*128;
    const __nv_bfloat16* A0h = Ah + aRow0*1024;
    const __nv_bfloat16* A0l = Al + aRow0*1024;
    const __nv_bfloat16* B0h = Bh + (long)blockIdx.z*Bbat + (long)blockIdx.x*128*1024;
    const __nv_bfloat16* B0l = Bl + (long)blockIdx.z*Bbat + (long)blockIdx.x*128*1024;

    float acc[2][8][4];
#pragma unroll
    for (int i=0;i<2;i++)
#pragma unroll
        for (int j=0;j<8;j++)
#pragma unroll
            for (int q=0;q<4;q++) acc[i][j][q]=0.f;

    // per-thread load geometry: 4 chunks of 16B for A and for B
    const int lrow = tid >> 3;           // base rows: lrow, lrow+32, +64, +96
    const int lc   = tid & 7;            // logical chunk 0..7

    // ---- pipeline ----
#pragma unroll 1
    for (int kt = 0; kt < 49; kt++){
        if (kt < 48){
            const int seg = kt >> 4;
            const int k0  = (kt & 15) * 64;
            const __nv_bfloat16* ap = (seg==1) ? A0l : A0h;
            const __nv_bfloat16* bp = (seg==2) ? B0l : B0h;
            const uint32_t da = sA + (kt & 1)*16384;
            const uint32_t db = sB + (kt & 1)*16384;
#pragma unroll
            for (int i = 0; i < 4; i++){
                const int row = lrow + i*32;
                const uint32_t o = (uint32_t)row*128 + (uint32_t)((lc ^ (row & 7))*16);
                cp16(da + o, ap + (long)row*1024 + k0 + lc*8);
                cp16(db + o, bp + (long)row*1024 + k0 + lc*8);
            }
            asm volatile("cp.async.commit_group;" ::: "memory");
        }
        if (kt == 0) continue;
        if (kt < 48) asm volatile("cp.async.wait_group 1;" ::: "memory");
        else         asm volatile("cp.async.wait_group 0;" ::: "memory");
        __syncthreads();

        // compute on buffer (kt-1)&1
        const uint32_t ca = sA + ((kt-1) & 1)*16384;
        const uint32_t cb = sB + ((kt-1) & 1)*16384;
#pragma unroll
        for (int ks = 0; ks < 4; ks++){
            const int kc = ks*2;
            uint32_t af[2][4], bf[4][4];
#pragma unroll
            for (int mi = 0; mi < 2; mi++){
                const int row = wm*32 + mi*16 + (lane & 15);
                const int c   = kc + (lane >> 4);
                ldsm4(af[mi], ca + row*128 + ((c ^ (row & 7))*16));
            }
#pragma unroll
            for (int ni = 0; ni < 4; ni++){
                const int row = wn*64 + ni*16 + (lane & 15);
                const int c   = kc + (lane >> 4);
                ldsm4(bf[ni], cb + row*128 + ((c ^ (row & 7))*16));
            }
#pragma unroll
            for (int mi = 0; mi < 2; mi++)
#pragma unroll
                for (int ni = 0; ni < 4; ni++){
                    mma16816(acc[mi][ni*2+0], af[mi], bf[ni][0], bf[ni][2]);
                    mma16816(acc[mi][ni*2+1], af[mi], bf[ni][1], bf[ni][3]);
                }
        }
        __syncthreads();
    }

    // ---- epilogue: alpha, optional -sub, write fp32 ----
    const long rb = (long)blockIdx.y*128 + wm*32 + (lane >> 2);
    const long cbase = (long)blockIdx.x*128 + wn*64 + (lane & 3)*2;
    float* Cp = C + Cbat*blockIdx.z;
#pragma unroll
    for (int mi = 0; mi < 2; mi++)
#pragma unroll
        for (int ni = 0; ni < 8; ni++){
            const long r = rb + mi*16;
            const long cc = cbase + ni*8;
            float2 v0, v1;
            v0.x = alpha*acc[mi][ni][0]; v0.y = alpha*acc[mi][ni][1];
            v1.x = alpha*acc[mi][ni][2]; v1.y = alpha*acc[mi][ni][3];
            if (sub){
                v0.x -= sub[r*2048 + cc];     v0.y -= sub[r*2048 + cc + 1];
                v1.x -= sub[(r+8)*2048 + cc]; v1.y -= sub[(r+8)*2048 + cc + 1];
            }
            *(float2*)(Cp + r*2048 + cc)     = v0;
            *(float2*)(Cp + (r+8)*2048 + cc) = v1;
        }
}

// ---------------- split fp32 -> (hi, lo) bf16 ------------------------------
__global__ void split_k(const float* __restrict__ in, __nv_bfloat16* __restrict__ oh,
                        __nv_bfloat16* __restrict__ ol){
    int idx = blockIdx.x*256 + threadIdx.x;
    float v = in[idx];
    __nv_bfloat16 h = __float2bfloat16_rn(v);
    oh[idx] = h;
    ol[idx] = __float2bfloat16_rn(v - __bfloat162float(h));
}

// ---------------- transpose + split ----------------------------------------
__global__ void tsplit_k(const float* __restrict__ in, __nv_bfloat16* __restrict__ oh,
                         __nv_bfloat16* __restrict__ ol, int R, int Cc,
                         long inZ, long outZ){
    __shared__ float t[32][33];
    const float* ip = in + inZ*blockIdx.z;
    __nv_bfloat16* hp = oh + outZ*blockIdx.z;
    __nv_bfloat16* lp = ol + outZ*blockIdx.z;
    int c0 = blockIdx.x*32, r0 = blockIdx.y*32;
    int tx = threadIdx.x, ty = threadIdx.y;
#pragma unroll
    for (int i = 0; i < 32; i += 8)
        t[ty+i][tx] = ip[(long)(r0+ty+i)*Cc + c0+tx];
    __syncthreads();
#pragma unroll
    for (int i = 0; i < 32; i += 8){
        float v = t[tx][ty+i];
        __nv_bfloat16 h = __float2bfloat16_rn(v);
        long o = (long)(c0+ty+i)*R + r0+tx;
        hp[o] = h;
        lp[o] = __float2bfloat16_rn(v - __bfloat162float(h));
    }
}

// ---------------- legacy FFMA SGEMM (K=64 paths) ---------------------------
__global__ __launch_bounds__(256) void sgemm_k(
    const float* __restrict__ A, const float* __restrict__ B, float* __restrict__ C,
    const float* __restrict__ sub, int N, int K, float alpha,
    long Abat, long Bbat, long Cbat)
{
    __shared__ float As[8][128];
    __shared__ float Bs[8][128];
    const int tid = threadIdx.x;
    const float* Ap = A + Abat*blockIdx.z + (long)(blockIdx.y*128)*K;
    const float* Bp = B + Bbat*blockIdx.z + blockIdx.x*128;
    float* Cp = C + Cbat*blockIdx.z;

    float acc[8][8];
#pragma unroll
    for (int i=0;i<8;i++)
#pragma unroll
        for (int j=0;j<8;j++) acc[i][j]=0.f;

    const int arow = tid>>1, acol=(tid&1)*4;
    const int brow = tid>>5, bcol=(tid&31)*4;
    const int ty = tid>>4, tx = tid&15;

    for (int k0=0;k0<K;k0+=8){
        float4 av = *(const float4*)(Ap + (long)arow*K + k0 + acol);
        As[acol+0][arow]=av.x; As[acol+1][arow]=av.y;
        As[acol+2][arow]=av.z; As[acol+3][arow]=av.w;
        *(float4*)&Bs[brow][bcol] = *(const float4*)(Bp + (long)(k0+brow)*N + bcol);
        __syncthreads();
#pragma unroll
        for (int kk=0;kk<8;kk++){
            float a[8],b[8];
#pragma unroll
            for(int i=0;i<8;i++) a[i]=As[kk][ty*8+i];
#pragma unroll
            for(int j=0;j<8;j++) b[j]=Bs[kk][tx*8+j];
#pragma unroll
            for(int i=0;i<8;i++)
#pragma unroll
                for(int j=0;j<8;j++) acc[i][j] = fmaf(a[i],b[j],acc[i][j]);
        }
        __syncthreads();
    }
#pragma unroll
    for(int i=0;i<8;i++){
        int row = blockIdx.y*128 + ty*8 + i;
#pragma unroll
        for(int j=0;j<8;j+=4){
            int col = blockIdx.x*128 + tx*8 + j;
            float4 v;
            v.x = alpha*acc[i][j];   v.y = alpha*acc[i][j+1];
            v.z = alpha*acc[i][j+2]; v.w = alpha*acc[i][j+3];
            if (sub){
                const float* s = sub + (long)row*N + col;
                v.x -= s[0]; v.y -= s[1]; v.z -= s[2]; v.w -= s[3];
            }
            *(float4*)(Cp + (long)row*N + col) = v;
        }
    }
}

// ---------------- row softmax of relu(row) ---------------------------------
__global__ void relu_softmax_k(const float* __restrict__ in, float* __restrict__ out){
    const int row = blockIdx.x;
    const int tid = threadIdx.x;
    __shared__ float red[256];
    const float* r = in + (long)row*NN;
    float mx = 0.f;
    for (int j=tid;j<NN;j+=256) mx = fmaxf(mx, r[j]);
    red[tid]=mx; __syncthreads();
    for (int s=128;s>0;s>>=1){ if(tid<s) red[tid]=fmaxf(red[tid],red[tid+s]); __syncthreads(); }
    mx = fmaxf(red[0], 0.f);
    __syncthreads();
    float sum=0.f;
    for (int j=tid;j<NN;j+=256) sum += expf(fmaxf(r[j],0.f)-mx);
    red[tid]=sum; __syncthreads();
    for (int s=128;s>0;s>>=1){ if(tid<s) red[tid]+=red[tid+s]; __syncthreads(); }
    float inv = 1.f/red[0];
    for (int j=tid;j<NN;j+=256) out[(long)row*NN+j] = expf(fmaxf(r[j],0.f)-mx)*inv;
}

// ---------------- x[B,N,T] -> X[N, B*T] ------------------------------------
__global__ void txpose_x_k(const float* __restrict__ x, float* __restrict__ X){
    int idx = blockIdx.x*256 + threadIdx.x;
    ((float4*)X)[idx] = ((const float4*)x)[((long)((idx>>4)&31)*NN + (idx>>9))*16 + (idx&15)];
}

// ---------------- E[N,D] -> ET[D,N] ----------------------------------------
__global__ void tE_k(const float* __restrict__ E, float* __restrict__ ET){
    int idx = blockIdx.x*256+threadIdx.x;
    int n = idx>>6, d = idx&63;
    ET[d*NN+n]=E[idx];
}

// ---------------- gather W -> Wmod -----------------------------------------
__global__ void wmod_k(const float* __restrict__ W, float* __restrict__ Wm){
    int idx = blockIdx.x*256 + threadIdx.x;
    if (idx >= DD*WCOLS) return;
    int d = idx / WCOLS;
    int r = idx - d*WCOLS;
    int ch = r >> 12;
    int to = r & 4095;
    float val;
    if (ch==0){
        val = W[(long)(d*3)*4096 + to] + W[(long)((64+d)*3)*4096 + to];
    } else {
        int g = (ch-1)&1;
        int k = 1 + ((ch-1)>>1);
        val = W[(long)((g*64+d)*3+k)*4096 + to];
    }
    Wm[idx] = val;
}

// ---------------- bias -----------------------------------------------------
__global__ void bias_k(const float* __restrict__ E, const float* __restrict__ bp,
                       float* __restrict__ bias){
    int n = blockIdx.x, o = threadIdx.x;
    float s = 0.f;
    for (int d=0; d<64; d++) s += E[n*64+d]*(bp[d*64+o] + bp[4096 + d*64+o]);
    bias[n*64+o]=s;
}

// ---------------- per-node contraction -------------------------------------
__global__ __launch_bounds__(256) void contract_k(
    const float* __restrict__ X, const float* __restrict__ Y,
    const float* __restrict__ Wc, const float* __restrict__ bias,
    float* __restrict__ O)
{
    const int n = blockIdx.x;
    const int tid = threadIdx.x;
    __shared__ float Xs[2048];
    __shared__ float Ws[4096];
    float acc[8]={0.f,0.f,0.f,0.f,0.f,0.f,0.f,0.f};
    const int b = tid>>3;
    const int ob = (tid&7)*8;
    for (int ch=0; ch<NCH; ch++){
        const float4* s4 = (const float4*)((ch==0)? X + (long)n*BT
                                                  : Y + ((long)(ch-1)*NN + n)*BT);
        ((float4*)Xs)[tid]     = s4[tid];
        ((float4*)Xs)[tid+256] = s4[tid+256];
        const float4* w4 = (const float4*)(Wc + (long)n*WCOLS + ch*4096);
#pragma unroll
        for (int q=0;q<4;q++) ((float4*)Ws)[tid + q*256] = w4[tid + q*256];
        __syncthreads();
#pragma unroll
        for (int t=0;t<64;t++){
            float xv = Xs[b*64+t];
            float4 w0 = *(const float4*)&Ws[t*64+ob];
            float4 w1 = *(const float4*)&Ws[t*64+ob+4];
            acc[0]=fmaf(xv,w0.x,acc[0]); acc[1]=fmaf(xv,w0.y,acc[1]);
            acc[2]=fmaf(xv,w0.z,acc[2]); acc[3]=fmaf(xv,w0.w,acc[3]);
            acc[4]=fmaf(xv,w1.x,acc[4]); acc[5]=fmaf(xv,w1.y,acc[5]);
            acc[6]=fmaf(xv,w1.z,acc[6]); acc[7]=fmaf(xv,w1.w,acc[7]);
        }
        __syncthreads();
    }
    float* o = O + ((long)n*BB + b)*FT + ob;
    const float* bi = bias + n*FT + ob;
#pragma unroll
    for (int j=0;j<8;j++) o[j] = acc[j] + bi[j];
}

// ---------------- layer1 epilogue ------------------------------------------
__global__ void proj_ln_relu_k(const float* __restrict__ O, const float* __restrict__ pw,
                               const float* __restrict__ pb, const float* __restrict__ gam,
                               const float* __restrict__ bet, float* __restrict__ Xout)
{
    const int nb = blockIdx.x;
    const int t = threadIdx.x;
    __shared__ float v[64], r1[64], r2[64];
    v[t] = O[(long)nb*64 + t];
    __syncthreads();
    float h = pb[t];
#pragma unroll
    for (int o=0;o<64;o++) h = fmaf(v[o], pw[o*64+t], h);
    r1[t]=h; r2[t]=h*h; __syncthreads();
    for (int s=32;s>0;s>>=1){ if(t<s){ r1[t]+=r1[t+s]; r2[t]+=r2[t+s]; } __syncthreads(); }
    float m = r1[0]*0.015625f;
    float var = r2[0]*0.015625f - m*m;
    float y = (h-m)*rsqrtf(var+1e-5f)*gam[t]+bet[t];
    y = fmaxf(y,0.f);
    const int n = nb>>5, b = nb&31;
    Xout[(long)n*BT + b*64 + t] = y;
}

// ---------------- layer2 epilogue ------------------------------------------
__global__ void final_k(const float* __restrict__ O, const float* __restrict__ pw,
                        const float* __restrict__ pb, const float* __restrict__ x,
                        const float* __restrict__ rg, const float* __restrict__ gam,
                        const float* __restrict__ bet, float* __restrict__ out)
{
    const int nb = blockIdx.x;
    const int t = threadIdx.x;
    const int n = nb>>5, b = nb&31;
    __shared__ float v[64], r1[64], r2[64];
    v[t]=O[(long)nb*64+t];
    __syncthreads();
    float h = pb[t];
#pragma unroll
    for (int o=0;o<64;o++) h = fmaf(v[o], pw[o*64+t], h);
    float sg = 1.f/(1.f+expf(-rg[0]));
    h = fmaf(sg, x[((long)b*NN+n)*64 + t], h);
    r1[t]=h; r2[t]=h*h; __syncthreads();
    for (int s=32;s>0;s>>=1){ if(t<s){ r1[t]+=r1[t+s]; r2[t]+=r2[t+s]; } __syncthreads(); }
    float m=r1[0]*0.015625f, var=r2[0]*0.015625f-m*m;
    out[((long)b*NN+n)*64+t] = (h-m)*rsqrtf(var+1e-5f)*gam[t]+bet[t];
}

// ===========================================================================
extern "C" void kernel_launch(void* const* d_in, const int* in_sizes, int n_in,
                              void* d_out, int out_size)
{
    const float* x     = (const float*)d_in[0];
    const float* A_fix = (const float*)d_in[1];
    const float* E     = (const float*)d_in[2];
    const float* W1    = (const float*)d_in[3];
    const float* b1p   = (const float*)d_in[4];
    const float* W2    = (const float*)d_in[5];
    const float* b2p   = (const float*)d_in[6];
    const float* p1w   = (const float*)d_in[7];
    const float* p1b   = (const float*)d_in[8];
    const float* p2w   = (const float*)d_in[9];
    const float* p2b   = (const float*)d_in[10];
    const float* g1    = (const float*)d_in[11];
    const float* be1   = (const float*)d_in[12];
    const float* g2    = (const float*)d_in[13];
    const float* be2   = (const float*)d_in[14];
    const float* rg    = (const float*)d_in[15];
    float* out = (float*)d_out;

    float *Xb,*Yb,*Sc,*Wm,*Wc,*Ob,*Bi,*ETp;
    __nv_bfloat16 *SH,*SL,*BH,*BL;
    cudaGetSymbolAddress((void**)&Xb,  g_Xbuf);
    cudaGetSymbolAddress((void**)&Yb,  g_Ybuf);
    cudaGetSymbolAddress((void**)&Sc,  g_Scat);
    cudaGetSymbolAddress((void**)&Wm,  g_Wmod);
    cudaGetSymbolAddress((void**)&Wc,  g_Wcat);
    cudaGetSymbolAddress((void**)&Ob,  g_Obuf);
    cudaGetSymbolAddress((void**)&Bi,  g_bias);
    cudaGetSymbolAddress((void**)&ETp, g_ET);
    cudaGetSymbolAddress((void**)&SH,  g_SH);
    cudaGetSymbolAddress((void**)&SL,  g_SL);
    cudaGetSymbolAddress((void**)&BH,  g_BH);
    cudaGetSymbolAddress((void**)&BL,  g_BL);

    cudaFuncSetAttribute(gemm_mma_k, cudaFuncAttributeMaxDynamicSharedMemorySize, 65536);
    const int MMSM = 65536;

    // --- supports ---
    tE_k<<<256,256>>>(E, ETp);
    sgemm_k<<<dim3(8,8,1),256>>>(E, ETp, Yb, nullptr, 1024, 64, 1.f, 0,0,0);
    relu_softmax_k<<<1024,256>>>(Yb,    Sc);
    relu_softmax_k<<<1024,256>>>(A_fix, Sc + (long)NN*NN);
    split_k<<<(2048*1024)/256,256>>>(Sc, SH, SL);

    // --- X node-major + transposed split ---
    txpose_x_k<<<2048,256>>>(x, Xb);
    tsplit_k<<<dim3(64,32,1),dim3(32,8)>>>(Xb, BH, BL, 1024, 2048, 0, 0);

    // --- layer 1 ---
    wmod_k<<<(DD*WCOLS+255)/256,256>>>(W1, Wm);
    sgemm_k<<<dim3(160,8,1),256>>>(E, Wm, Wc, nullptr, WCOLS, 64, 1.f, 0,0,0);
    bias_k<<<1024,64>>>(E, b1p, Bi);
    // Y1 = [S0;S1] @ X
    gemm_mma_k<<<dim3(16,16,1),256,MMSM>>>(SH, SL, BH, BL, Yb, nullptr, 1.f, 0, 0, 0);
    tsplit_k<<<dim3(64,32,2),dim3(32,8)>>>(Yb, BH, BL, 1024, 2048,
                                           (long)NN*BT, 2048L*1024);
    // Y2_g = 2*S_g@Y1_g - X
    gemm_mma_k<<<dim3(16,8,2),256,MMSM>>>(SH, SL, BH, BL, Yb + 2L*NN*BT, Xb, 2.f,
                                          1024, 2048L*1024, (long)NN*BT);
    contract_k<<<1024,256>>>(Xb, Yb, Wc, Bi, Ob);
    proj_ln_relu_k<<<NN*BB,64>>>(Ob, p1w, p1b, g1, be1, Xb);

    // --- layer 2 ---
    wmod_k<<<(DD*WCOLS+255)/256,256>>>(W2, Wm);
    sgemm_k<<<dim3(160,8,1),256>>>(E, Wm, Wc, nullptr, WCOLS, 64, 1.f, 0,0,0);
    bias_k<<<1024,64>>>(E, b2p, Bi);
    tsplit_k<<<dim3(64,32,1),dim3(32,8)>>>(Xb, BH, BL, 1024, 2048, 0, 0);
    gemm_mma_k<<<dim3(16,16,1),256,MMSM>>>(SH, SL, BH, BL, Yb, nullptr, 1.f, 0, 0, 0);
    tsplit_k<<<dim3(64,32,2),dim3(32,8)>>>(Yb, BH, BL, 1024, 2048,
                                           (long)NN*BT, 2048L*1024);
    gemm_mma_k<<<dim3(16,8,2),256,MMSM>>>(SH, SL, BH, BL, Yb + 2L*NN*BT, Xb, 2.f,
                                          1024, 2048L*1024, (long)NN*BT);
    contract_k<<<1024,256>>>(Xb, Yb, Wc, Bi, Ob);
    final_k<<<NN*BB,64>>>(Ob, p2w, p2b, x, rg, g2, be2, out);
}

// round 7
// speedup vs baseline: 1.6812x; 1.0631x over previous
#include <cuda_runtime.h>
#include <cuda_bf16.h>
#include <math.h>
#include <stdint.h>

// Problem constants
#define NN 1024
#define TT 64
#define BB 32
#define DD 64
#define FT 64
#define BT 2048
#define NCH 5
#define WCOLS (NCH*TT*FT)   // 20480

// ---------------- scratch (device globals) ---------------------------------
__device__ float g_Xbuf[NN*BT];
__device__ float g_Ybuf[4*NN*BT];
__device__ float g_Scat[2*NN*NN];
__device__ float g_Wmod[DD*WCOLS];
__device__ float g_Wcat[(size_t)NN*WCOLS];
__device__ float g_Obuf[NN*BB*FT];
__device__ float g_bias[NN*FT];
// split-bf16 operand planes
__device__ __nv_bfloat16 g_SH[2048*1024];      // S hi  [2048,1024]
__device__ __nv_bfloat16 g_SL[2048*1024];
__device__ __nv_bfloat16 g_BH[2*2048*1024];    // data operand hi [z][2048,1024]
__device__ __nv_bfloat16 g_BL[2*2048*1024];
__device__ __nv_bfloat16 g_EH[1024*64];        // E split
__device__ __nv_bfloat16 g_EL[1024*64];
__device__ __nv_bfloat16 g_WTH[WCOLS*64];      // Wmod^T split [20480,64]
__device__ __nv_bfloat16 g_WTL[WCOLS*64];

// ---------------- helpers ---------------------------------------------------
__device__ __forceinline__ uint32_t s2u(const void* p){
    uint32_t a;
    asm("{ .reg .u64 t; cvta.to.shared.u64 t, %1; cvt.u32.u64 %0, t; }" : "=r"(a) : "l"(p));
    return a;
}
__device__ __forceinline__ void cp16(uint32_t s, const void* g){
    asm volatile("cp.async.cg.shared.global [%0], [%1], 16;" :: "r"(s), "l"(g));
}
__device__ __forceinline__ void ldsm4(uint32_t* r, uint32_t a){
    asm volatile("ldmatrix.sync.aligned.m8n8.x4.shared.b16 {%0,%1,%2,%3}, [%4];"
        : "=r"(r[0]), "=r"(r[1]), "=r"(r[2]), "=r"(r[3]) : "r"(a));
}
__device__ __forceinline__ void mma16816(float* d, const uint32_t* a, uint32_t b0, uint32_t b1){
    asm volatile("mma.sync.aligned.m16n8k16.row.col.f32.bf16.bf16.f32 "
        "{%0,%1,%2,%3}, {%4,%5,%6,%7}, {%8,%9}, {%0,%1,%2,%3};"
        : "+f"(d[0]), "+f"(d[1]), "+f"(d[2]), "+f"(d[3])
        : "r"(a[0]), "r"(a[1]), "r"(a[2]), "r"(a[3]), "r"(b0), "r"(b1));
}

// ============ generic split-bf16 GEMM on mma.sync ===========================
// C[M, N] = alpha * (Afp32 @ B^T) (- sub), 3-segment split bf16.
// A planes [Mtot, Kdim] K-major; B planes [Ntot, Kdim] K-major (row = out col).
// grid (N/128, M/128, z), 256 thr. CTA tile 128x128, warp 32x64, k-stage 64.
__global__ void __launch_bounds__(256,2) gemm_mma_k(
    const __nv_bfloat16* __restrict__ Ah, const __nv_bfloat16* __restrict__ Al,
    const __nv_bfloat16* __restrict__ Bh, const __nv_bfloat16* __restrict__ Bl,
    float* __restrict__ C, const float* __restrict__ sub,
    float alpha, int Kdim, int kTiles, int ldc,
    int AzRows, long Bbat, long Cbat)
{
    extern __shared__ __align__(16) char smraw[];
    const uint32_t sA = s2u(smraw);              // [2][128][64] bf16 = 2x16KB
    const uint32_t sB = sA + 32768;

    const int tid  = threadIdx.x;
    const int wid  = tid >> 5;
    const int lane = tid & 31;
    const int wm   = wid >> 1;          // 0..3
    const int wn   = wid & 1;           // 0..1

    const long aRow0 = (long)blockIdx.z*AzRows + (long)blockIdx.y*128;
    const __nv_bfloat16* A0h = Ah + aRow0*Kdim;
    const __nv_bfloat16* A0l = Al + aRow0*Kdim;
    const __nv_bfloat16* B0h = Bh + (long)blockIdx.z*Bbat + (long)blockIdx.x*128*Kdim;
    const __nv_bfloat16* B0l = Bl + (long)blockIdx.z*Bbat + (long)blockIdx.x*128*Kdim;

    float acc[2][8][4];
#pragma unroll
    for (int i=0;i<2;i++)
#pragma unroll
        for (int j=0;j<8;j++)
#pragma unroll
            for (int q=0;q<4;q++) acc[i][j][q]=0.f;

    const int lrow = tid >> 3;           // base rows: lrow, +32, +64, +96
    const int lc   = tid & 7;            // 16B chunk 0..7

    const int iters = 3*kTiles;
#pragma unroll 1
    for (int kt = 0; kt <= iters; kt++){
        if (kt < iters){
            const int seg = kt / kTiles;
            const int k0  = (kt - seg*kTiles) * 64;
            const __nv_bfloat16* ap = (seg==1) ? A0l : A0h;
            const __nv_bfloat16* bp = (seg==2) ? B0l : B0h;
            const uint32_t da = sA + (kt & 1)*16384;
            const uint32_t db = sB + (kt & 1)*16384;
#pragma unroll
            for (int i = 0; i < 4; i++){
                const int row = lrow + i*32;
                const uint32_t o = (uint32_t)row*128 + (uint32_t)((lc ^ (row & 7))*16);
                cp16(da + o, ap + (long)row*Kdim + k0 + lc*8);
                cp16(db + o, bp + (long)row*Kdim + k0 + lc*8);
            }
            asm volatile("cp.async.commit_group;" ::: "memory");
        }
        if (kt == 0) continue;
        if (kt < iters) asm volatile("cp.async.wait_group 1;" ::: "memory");
        else            asm volatile("cp.async.wait_group 0;" ::: "memory");
        __syncthreads();

        const uint32_t ca = sA + ((kt-1) & 1)*16384;
        const uint32_t cb = sB + ((kt-1) & 1)*16384;
#pragma unroll
        for (int ks = 0; ks < 4; ks++){
            const int kc = ks*2;
            uint32_t af[2][4], bf[4][4];
#pragma unroll
            for (int mi = 0; mi < 2; mi++){
                const int row = wm*32 + mi*16 + (lane & 15);
                const int c   = kc + (lane >> 4);
                ldsm4(af[mi], ca + row*128 + ((c ^ (row & 7))*16));
            }
#pragma unroll
            for (int ni = 0; ni < 4; ni++){
                const int row = wn*64 + ni*16 + (lane & 15);
                const int c   = kc + (lane >> 4);
                ldsm4(bf[ni], cb + row*128 + ((c ^ (row & 7))*16));
            }
#pragma unroll
            for (int mi = 0; mi < 2; mi++)
#pragma unroll
                for (int ni = 0; ni < 4; ni++){
                    mma16816(acc[mi][ni*2+0], af[mi], bf[ni][0], bf[ni][2]);
                    mma16816(acc[mi][ni*2+1], af[mi], bf[ni][1], bf[ni][3]);
                }
        }
        __syncthreads();
    }

    // ---- epilogue ----
    const long rb = (long)blockIdx.y*128 + wm*32 + (lane >> 2);
    const long cbase = (long)blockIdx.x*128 + wn*64 + (lane & 3)*2;
    float* Cp = C + Cbat*blockIdx.z;
#pragma unroll
    for (int mi = 0; mi < 2; mi++)
#pragma unroll
        for (int ni = 0; ni < 8; ni++){
            const long r = rb + mi*16;
            const long cc = cbase + ni*8;
            float2 v0, v1;
            v0.x = alpha*acc[mi][ni][0]; v0.y = alpha*acc[mi][ni][1];
            v1.x = alpha*acc[mi][ni][2]; v1.y = alpha*acc[mi][ni][3];
            if (sub){
                v0.x -= sub[r*ldc + cc];     v0.y -= sub[r*ldc + cc + 1];
                v1.x -= sub[(r+8)*ldc + cc]; v1.y -= sub[(r+8)*ldc + cc + 1];
            }
            *(float2*)(Cp + r*ldc + cc)     = v0;
            *(float2*)(Cp + (r+8)*ldc + cc) = v1;
        }
}

// ---------------- split fp32 -> (hi, lo) bf16 ------------------------------
__global__ void split_k(const float* __restrict__ in, __nv_bfloat16* __restrict__ oh,
                        __nv_bfloat16* __restrict__ ol){
    int idx = blockIdx.x*256 + threadIdx.x;
    float v = in[idx];
    __nv_bfloat16 h = __float2bfloat16_rn(v);
    oh[idx] = h;
    ol[idx] = __float2bfloat16_rn(v - __bfloat162float(h));
}

// ---------------- transpose + split: in [R,Cc] fp32 -> out [Cc,R] hi/lo ----
__global__ void tsplit_k(const float* __restrict__ in, __nv_bfloat16* __restrict__ oh,
                         __nv_bfloat16* __restrict__ ol, int R, int Cc,
                         long inZ, long outZ){
    __shared__ float t[32][33];
    const float* ip = in + inZ*blockIdx.z;
    __nv_bfloat16* hp = oh + outZ*blockIdx.z;
    __nv_bfloat16* lp = ol + outZ*blockIdx.z;
    int c0 = blockIdx.x*32, r0 = blockIdx.y*32;
    int tx = threadIdx.x, ty = threadIdx.y;
#pragma unroll
    for (int i = 0; i < 32; i += 8)
        t[ty+i][tx] = ip[(long)(r0+ty+i)*Cc + c0+tx];
    __syncthreads();
#pragma unroll
    for (int i = 0; i < 32; i += 8){
        float v = t[tx][ty+i];
        __nv_bfloat16 h = __float2bfloat16_rn(v);
        long o = (long)(c0+ty+i)*R + r0+tx;
        hp[o] = h;
        lp[o] = __float2bfloat16_rn(v - __bfloat162float(h));
    }
}

// ---------------- row softmax of relu(row) ---------------------------------
__global__ void relu_softmax_k(const float* __restrict__ in, float* __restrict__ out){
    const int row = blockIdx.x;
    const int tid = threadIdx.x;
    __shared__ float red[256];
    const float* r = in + (long)row*NN;
    float mx = 0.f;
    for (int j=tid;j<NN;j+=256) mx = fmaxf(mx, r[j]);
    red[tid]=mx; __syncthreads();
    for (int s=128;s>0;s>>=1){ if(tid<s) red[tid]=fmaxf(red[tid],red[tid+s]); __syncthreads(); }
    mx = fmaxf(red[0], 0.f);
    __syncthreads();
    float sum=0.f;
    for (int j=tid;j<NN;j+=256) sum += expf(fmaxf(r[j],0.f)-mx);
    red[tid]=sum; __syncthreads();
    for (int s=128;s>0;s>>=1){ if(tid<s) red[tid]+=red[tid+s]; __syncthreads(); }
    float inv = 1.f/red[0];
    for (int j=tid;j<NN;j+=256) out[(long)row*NN+j] = expf(fmaxf(r[j],0.f)-mx)*inv;
}

// ---------------- x[B,N,T] -> X[N, B*T] ------------------------------------
__global__ void txpose_x_k(const float* __restrict__ x, float* __restrict__ X){
    int idx = blockIdx.x*256 + threadIdx.x;
    ((float4*)X)[idx] = ((const float4*)x)[((long)((idx>>4)&31)*NN + (idx>>9))*16 + (idx&15)];
}

// ---------------- gather W -> Wmod [64, 20480] -----------------------------
__global__ void wmod_k(const float* __restrict__ W, float* __restrict__ Wm){
    int idx = blockIdx.x*256 + threadIdx.x;
    if (idx >= DD*WCOLS) return;
    int d = idx / WCOLS;
    int r = idx - d*WCOLS;
    int ch = r >> 12;
    int to = r & 4095;
    float val;
    if (ch==0){
        val = W[(long)(d*3)*4096 + to] + W[(long)((64+d)*3)*4096 + to];
    } else {
        int g = (ch-1)&1;
        int k = 1 + ((ch-1)>>1);
        val = W[(long)((g*64+d)*3+k)*4096 + to];
    }
    Wm[idx] = val;
}

// ---------------- bias -----------------------------------------------------
__global__ void bias_k(const float* __restrict__ E, const float* __restrict__ bp,
                       float* __restrict__ bias){
    int n = blockIdx.x, o = threadIdx.x;
    float s = 0.f;
    for (int d=0; d<64; d++) s += E[n*64+d]*(bp[d*64+o] + bp[4096 + d*64+o]);
    bias[n*64+o]=s;
}

// ---------------- per-node contraction -------------------------------------
__global__ __launch_bounds__(256) void contract_k(
    const float* __restrict__ X, const float* __restrict__ Y,
    const float* __restrict__ Wc, const float* __restrict__ bias,
    float* __restrict__ O)
{
    const int n = blockIdx.x;
    const int tid = threadIdx.x;
    __shared__ float Xs[2048];
    __shared__ float Ws[4096];
    float acc[8]={0.f,0.f,0.f,0.f,0.f,0.f,0.f,0.f};
    const int b = tid>>3;
    const int ob = (tid&7)*8;
    for (int ch=0; ch<NCH; ch++){
        const float4* s4 = (const float4*)((ch==0)? X + (long)n*BT
                                                  : Y + ((long)(ch-1)*NN + n)*BT);
        ((float4*)Xs)[tid]     = s4[tid];
        ((float4*)Xs)[tid+256] = s4[tid+256];
        const float4* w4 = (const float4*)(Wc + (long)n*WCOLS + ch*4096);
#pragma unroll
        for (int q=0;q<4;q++) ((float4*)Ws)[tid + q*256] = w4[tid + q*256];
        __syncthreads();
#pragma unroll
        for (int t=0;t<64;t++){
            float xv = Xs[b*64+t];
            float4 w0 = *(const float4*)&Ws[t*64+ob];
            float4 w1 = *(const float4*)&Ws[t*64+ob+4];
            acc[0]=fmaf(xv,w0.x,acc[0]); acc[1]=fmaf(xv,w0.y,acc[1]);
            acc[2]=fmaf(xv,w0.z,acc[2]); acc[3]=fmaf(xv,w0.w,acc[3]);
            acc[4]=fmaf(xv,w1.x,acc[4]); acc[5]=fmaf(xv,w1.y,acc[5]);
            acc[6]=fmaf(xv,w1.z,acc[6]); acc[7]=fmaf(xv,w1.w,acc[7]);
        }
        __syncthreads();
    }
    float* o = O + ((long)n*BB + b)*FT + ob;
    const float* bi = bias + n*FT + ob;
#pragma unroll
    for (int j=0;j<8;j++) o[j] = acc[j] + bi[j];
}

// ---------------- layer1 epilogue ------------------------------------------
__global__ void proj_ln_relu_k(const float* __restrict__ O, const float* __restrict__ pw,
                               const float* __restrict__ pb, const float* __restrict__ gam,
                               const float* __restrict__ bet, float* __restrict__ Xout)
{
    const int nb = blockIdx.x;
    const int t = threadIdx.x;
    __shared__ float v[64], r1[64], r2[64];
    v[t] = O[(long)nb*64 + t];
    __syncthreads();
    float h = pb[t];
#pragma unroll
    for (int o=0;o<64;o++) h = fmaf(v[o], pw[o*64+t], h);
    r1[t]=h; r2[t]=h*h; __syncthreads();
    for (int s=32;s>0;s>>=1){ if(t<s){ r1[t]+=r1[t+s]; r2[t]+=r2[t+s]; } __syncthreads(); }
    float m = r1[0]*0.015625f;
    float var = r2[0]*0.015625f - m*m;
    float y = (h-m)*rsqrtf(var+1e-5f)*gam[t]+bet[t];
    y = fmaxf(y,0.f);
    const int n = nb>>5, b = nb&31;
    Xout[(long)n*BT + b*64 + t] = y;
}

// ---------------- layer2 epilogue ------------------------------------------
__global__ void final_k(const float* __restrict__ O, const float* __restrict__ pw,
                        const float* __restrict__ pb, const float* __restrict__ x,
                        const float* __restrict__ rg, const float* __restrict__ gam,
                        const float* __restrict__ bet, float* __restrict__ out)
{
    const int nb = blockIdx.x;
    const int t = threadIdx.x;
    const int n = nb>>5, b = nb&31;
    __shared__ float v[64], r1[64], r2[64];
    v[t]=O[(long)nb*64+t];
    __syncthreads();
    float h = pb[t];
#pragma unroll
    for (int o=0;o<64;o++) h = fmaf(v[o], pw[o*64+t], h);
    float sg = 1.f/(1.f+expf(-rg[0]));
    h = fmaf(sg, x[((long)b*NN+n)*64 + t], h);
    r1[t]=h; r2[t]=h*h; __syncthreads();
    for (int s=32;s>0;s>>=1){ if(t<s){ r1[t]+=r1[t+s]; r2[t]+=r2[t+s]; } __syncthreads(); }
    float m=r1[0]*0.015625f, var=r2[0]*0.015625f-m*m;
    out[((long)b*NN+n)*64+t] = (h-m)*rsqrtf(var+1e-5f)*gam[t]+bet[t];
}

// ===========================================================================
extern "C" void kernel_launch(void* const* d_in, const int* in_sizes, int n_in,
                              void* d_out, int out_size)
{
    const float* x     = (const float*)d_in[0];
    const float* A_fix = (const float*)d_in[1];
    const float* E     = (const float*)d_in[2];
    const float* W1    = (const float*)d_in[3];
    const float* b1p   = (const float*)d_in[4];
    const float* W2    = (const float*)d_in[5];
    const float* b2p   = (const float*)d_in[6];
    const float* p1w   = (const float*)d_in[7];
    const float* p1b   = (const float*)d_in[8];
    const float* p2w   = (const float*)d_in[9];
    const float* p2b   = (const float*)d_in[10];
    const float* g1    = (const float*)d_in[11];
    const float* be1   = (const float*)d_in[12];
    const float* g2    = (const float*)d_in[13];
    const float* be2   = (const float*)d_in[14];
    const float* rg    = (const float*)d_in[15];
    float* out = (float*)d_out;

    float *Xb,*Yb,*Sc,*Wm,*Wc,*Ob,*Bi;
    __nv_bfloat16 *SH,*SL,*BH,*BL,*EH,*EL,*WTH,*WTL;
    cudaGetSymbolAddress((void**)&Xb,  g_Xbuf);
    cudaGetSymbolAddress((void**)&Yb,  g_Ybuf);
    cudaGetSymbolAddress((void**)&Sc,  g_Scat);
    cudaGetSymbolAddress((void**)&Wm,  g_Wmod);
    cudaGetSymbolAddress((void**)&Wc,  g_Wcat);
    cudaGetSymbolAddress((void**)&Ob,  g_Obuf);
    cudaGetSymbolAddress((void**)&Bi,  g_bias);
    cudaGetSymbolAddress((void**)&SH,  g_SH);
    cudaGetSymbolAddress((void**)&SL,  g_SL);
    cudaGetSymbolAddress((void**)&BH,  g_BH);
    cudaGetSymbolAddress((void**)&BL,  g_BL);
    cudaGetSymbolAddress((void**)&EH,  g_EH);
    cudaGetSymbolAddress((void**)&EL,  g_EL);
    cudaGetSymbolAddress((void**)&WTH, g_WTH);
    cudaGetSymbolAddress((void**)&WTL, g_WTL);

    cudaFuncSetAttribute(gemm_mma_k, cudaFuncAttributeMaxDynamicSharedMemorySize, 65536);
    const int MMSM = 65536;

    // --- supports ---
    split_k<<<(NN*DD)/256,256>>>(E, EH, EL);                       // E split (shared)
    // EET = E@E^T (temp in Yb)
    gemm_mma_k<<<dim3(8,8,1),256,MMSM>>>(EH, EL, EH, EL, Yb, nullptr, 1.f,
                                         64, 1, 1024, 0, 0, 0);
    relu_softmax_k<<<1024,256>>>(Yb,    Sc);
    relu_softmax_k<<<1024,256>>>(A_fix, Sc + (long)NN*NN);
    split_k<<<(2048*1024)/256,256>>>(Sc, SH, SL);

    // --- X node-major + transposed split ---
    txpose_x_k<<<2048,256>>>(x, Xb);
    tsplit_k<<<dim3(64,32,1),dim3(32,8)>>>(Xb, BH, BL, 1024, 2048, 0, 0);

    // --- layer 1 ---
    wmod_k<<<(DD*WCOLS+255)/256,256>>>(W1, Wm);
    tsplit_k<<<dim3(640,2,1),dim3(32,8)>>>(Wm, WTH, WTL, 64, WCOLS, 0, 0);
    gemm_mma_k<<<dim3(160,8,1),256,MMSM>>>(EH, EL, WTH, WTL, Wc, nullptr, 1.f,
                                           64, 1, WCOLS, 0, 0, 0);
    bias_k<<<1024,64>>>(E, b1p, Bi);
    // Y1 = [S0;S1] @ X
    gemm_mma_k<<<dim3(16,16,1),256,MMSM>>>(SH, SL, BH, BL, Yb, nullptr, 1.f,
                                           1024, 16, 2048, 0, 0, 0);
    tsplit_k<<<dim3(64,32,2),dim3(32,8)>>>(Yb, BH, BL, 1024, 2048,
                                           (long)NN*BT, 2048L*1024);
    // Y2_g = 2*S_g@Y1_g - X
    gemm_mma_k<<<dim3(16,8,2),256,MMSM>>>(SH, SL, BH, BL, Yb + 2L*NN*BT, Xb, 2.f,
                                          1024, 16, 2048, 1024, 2048L*1024, (long)NN*BT);
    contract_k<<<1024,256>>>(Xb, Yb, Wc, Bi, Ob);
    proj_ln_relu_k<<<NN*BB,64>>>(Ob, p1w, p1b, g1, be1, Xb);

    // --- layer 2 ---
    wmod_k<<<(DD*WCOLS+255)/256,256>>>(W2, Wm);
    tsplit_k<<<dim3(640,2,1),dim3(32,8)>>>(Wm, WTH, WTL, 64, WCOLS, 0, 0);
    gemm_mma_k<<<dim3(160,8,1),256,MMSM>>>(EH, EL, WTH, WTL, Wc, nullptr, 1.f,
                                           64, 1, WCOLS, 0, 0, 0);
    bias_k<<<1024,64>>>(E, b2p, Bi);
    tsplit_k<<<dim3(64,32,1),dim3(32,8)>>>(Xb, BH, BL, 1024, 2048, 0, 0);
    gemm_mma_k<<<dim3(16,16,1),256,MMSM>>>(SH, SL, BH, BL, Yb, nullptr, 1.f,
                                           1024, 16, 2048, 0, 0, 0);
    tsplit_k<<<dim3(64,32,2),dim3(32,8)>>>(Yb, BH, BL, 1024, 2048,
                                           (long)NN*BT, 2048L*1024);
    gemm_mma_k<<<dim3(16,8,2),256,MMSM>>>(SH, SL, BH, BL, Yb + 2L*NN*BT, Xb, 2.f,
                                          1024, 16, 2048, 1024, 2048L*1024, (long)NN*BT);
    contract_k<<<1024,256>>>(Xb, Yb, Wc, Bi, Ob);
    final_k<<<NN*BB,64>>>(Ob, p2w, p2b, x, rg, g2, be2, out);
}